// round 12
// baseline (speedup 1.0000x reference)
#include <cuda_runtime.h>
#include <cuda_bf16.h>
#include <cstdint>

#define N_NODES 50000
#define N_EDGES 800000
#define IN_F 256
#define HEADS 4
#define OUT_F 64
#define HF 256            // HEADS * OUT_F
#define NEG_SLOPE 0.2f

#define SCAN_CHUNK 512
#define NBLK ((N_NODES + SCAN_CHUNK - 1) / SCAN_CHUNK)   // 98

// ---------------- scratch (static device allocations; no cudaMalloc) --------
__device__ float g_h[(size_t)N_NODES * HF];      // 51.2 MB  projected features
__device__ __nv_bfloat16 g_xhi[(size_t)N_NODES * IN_F];   // 25.6 MB
__device__ __nv_bfloat16 g_xlo[(size_t)N_NODES * IN_F];   // 25.6 MB
__device__ __nv_bfloat16 g_Whi[IN_F * HF];
__device__ __nv_bfloat16 g_Wlo[IN_F * HF];
__device__ float g_asrc[N_NODES * HEADS];
__device__ float g_adst[N_NODES * HEADS];
__device__ int   g_deg[N_NODES];
__device__ int   g_off[N_NODES + 1];
__device__ int   g_cursor[N_NODES];
__device__ int   g_csr[N_EDGES];                 // src ids grouped by dst
__device__ int   g_bsum[NBLK];
__device__ int   g_boff[NBLK];

// ---------------- split kernels: v -> bf16 hi + bf16 residual ---------------
__global__ void wsplit_kernel(const float* __restrict__ W) {
    int i = blockIdx.x * blockDim.x + threadIdx.x;
    if (i >= IN_F * HF) return;
    float w = W[i];
    __nv_bfloat16 hi = __float2bfloat16(w);
    __nv_bfloat16 lo = __float2bfloat16(w - __bfloat162float(hi));
    g_Whi[i] = hi;
    g_Wlo[i] = lo;
}

__global__ __launch_bounds__(256) void xsplit_kernel(const float* __restrict__ x) {
    // warp per node; lane owns 8 consecutive floats
    int n = (blockIdx.x * blockDim.x + threadIdx.x) >> 5;
    int lane = threadIdx.x & 31;
    if (n >= N_NODES) return;
    const float4* xr = (const float4*)(x + (size_t)n * IN_F) + lane * 2;
    float4 xa = xr[0], xb = xr[1];
    float xs[8] = {xa.x, xa.y, xa.z, xa.w, xb.x, xb.y, xb.z, xb.w};
    union { __nv_bfloat16 b[8]; uint4 u; } H, L;
#pragma unroll
    for (int i = 0; i < 8; i++) {
        H.b[i] = __float2bfloat16(xs[i]);
        L.b[i] = __float2bfloat16(xs[i] - __bfloat162float(H.b[i]));
    }
    *(uint4*)(g_xhi + (size_t)n * IN_F + lane * 8) = H.u;
    *(uint4*)(g_xlo + (size_t)n * IN_F + lane * 8) = L.u;
}

// ---------------- GEMM: g_h = x @ W via 3 bf16 tensor-core passes -----------
// hi*hi + hi*lo + lo*hi  (lo*lo dropped, ~2^-16 relative)
// blockIdx.y = head; fused a_src/a_dst epilogue (deterministic, no atomics).
#define ASTRIDE 40   // bf16 elements per A smem row (80B, conflict-free ldmatrix)
#define BSTRIDE 72   // bf16 elements per B smem row (144B)

__device__ __forceinline__ void ldsm4(uint32_t* r, const __nv_bfloat16* p) {
    unsigned a = (unsigned)__cvta_generic_to_shared(p);
    asm volatile("ldmatrix.sync.aligned.m8n8.x4.shared.b16 {%0,%1,%2,%3}, [%4];"
                 : "=r"(r[0]), "=r"(r[1]), "=r"(r[2]), "=r"(r[3]) : "r"(a));
}
__device__ __forceinline__ void ldsm4t(uint32_t* r, const __nv_bfloat16* p) {
    unsigned a = (unsigned)__cvta_generic_to_shared(p);
    asm volatile("ldmatrix.sync.aligned.m8n8.x4.trans.shared.b16 {%0,%1,%2,%3}, [%4];"
                 : "=r"(r[0]), "=r"(r[1]), "=r"(r[2]), "=r"(r[3]) : "r"(a));
}
__device__ __forceinline__ void mma16816(float* c, const uint32_t* a, uint32_t b0, uint32_t b1) {
    asm volatile("mma.sync.aligned.m16n8k16.row.col.f32.bf16.bf16.f32 "
                 "{%0,%1,%2,%3}, {%4,%5,%6,%7}, {%8,%9}, {%0,%1,%2,%3};"
                 : "+f"(c[0]), "+f"(c[1]), "+f"(c[2]), "+f"(c[3])
                 : "r"(a[0]), "r"(a[1]), "r"(a[2]), "r"(a[3]), "r"(b0), "r"(b1));
}

__global__ __launch_bounds__(256) void gemm_bf16_kernel(const float* __restrict__ att_s,
                                                        const float* __restrict__ att_d) {
    __shared__ __align__(16) __nv_bfloat16 sA[128 * ASTRIDE];  // 10240 B
    __shared__ __align__(16) __nv_bfloat16 sB[32 * BSTRIDE];   //  4608 B
    __shared__ float sds[2][128];   // per-(wn,row) a_src partials
    __shared__ float sdd[2][128];   // per-(wn,row) a_dst partials

    const int tid = threadIdx.x;
    const int lane = tid & 31;
    const int wid = tid >> 5;
    const int wm = wid & 3;        // 4 M-warps of 32 rows
    const int wn = wid >> 2;       // 2 N-warps of 32 cols
    const int mb = blockIdx.x * 128;
    const int hd = blockIdx.y;     // head; nb = hd*64
    const int nb = hd * 64;
    const int lrow = lane & 15;
    const int lcol8 = (lane >> 4) << 3;   // 0 or 8 (bf16 elements)

    float acc[2][4][4];
#pragma unroll
    for (int i = 0; i < 2; i++)
#pragma unroll
        for (int j = 0; j < 4; j++)
#pragma unroll
            for (int k = 0; k < 4; k++) acc[i][j][k] = 0.f;

#pragma unroll 1
    for (int seg = 0; seg < 3; seg++) {
        const __nv_bfloat16* Ag = (seg == 2) ? g_xlo : g_xhi;
        const __nv_bfloat16* Bg = (seg == 1) ? g_Wlo : g_Whi;
#pragma unroll 1
        for (int kt = 0; kt < IN_F; kt += 32) {
            // A tile: 128 rows x 32 bf16 = 512 x 16B chunks, 2 per thread
#pragma unroll
            for (int i = 0; i < 2; i++) {
                int c = tid + i * 256;
                int r = c >> 2, c16 = c & 3;
                int grow = mb + r;
                uint4 v = make_uint4(0, 0, 0, 0);
                if (grow < N_NODES)
                    v = *(const uint4*)(Ag + (size_t)grow * IN_F + kt + c16 * 8);
                *(uint4*)(sA + r * ASTRIDE + c16 * 8) = v;
            }
            // B tile: 32 rows x 64 bf16 = 256 x 16B chunks, 1 per thread
            {
                int r = tid >> 3, c16 = tid & 7;
                uint4 v = *(const uint4*)(Bg + (size_t)(kt + r) * HF + nb + c16 * 8);
                *(uint4*)(sB + r * BSTRIDE + c16 * 8) = v;
            }
            __syncthreads();

            uint32_t a[2][2][4], b[2][2][4];
#pragma unroll
            for (int mt = 0; mt < 2; mt++)
#pragma unroll
                for (int kc = 0; kc < 2; kc++)
                    ldsm4(a[mt][kc],
                          sA + (wm * 32 + mt * 16 + lrow) * ASTRIDE + kc * 16 + lcol8);
#pragma unroll
            for (int kc = 0; kc < 2; kc++)
#pragma unroll
                for (int nt2 = 0; nt2 < 2; nt2++)
                    ldsm4t(b[kc][nt2],
                           sB + (kc * 16 + lrow) * BSTRIDE + wn * 32 + nt2 * 16 + lcol8);
#pragma unroll
            for (int mt = 0; mt < 2; mt++)
#pragma unroll
                for (int nt = 0; nt < 4; nt++)
#pragma unroll
                    for (int kc = 0; kc < 2; kc++) {
                        uint32_t* bb = &b[kc][nt >> 1][(nt & 1) * 2];
                        mma16816(acc[mt][nt], a[mt][kc], bb[0], bb[1]);
                    }
            __syncthreads();
        }
    }

    // ---- epilogue: store g_h + fused attention dots ----
    const float* wsp = att_s + hd * OUT_F;
    const float* wdp = att_d + hd * OUT_F;

#pragma unroll
    for (int mt = 0; mt < 2; mt++) {
        int row0 = mb + wm * 32 + mt * 16 + (lane >> 2);
        float s0 = 0.f, s1 = 0.f, d0 = 0.f, d1 = 0.f;
#pragma unroll
        for (int nt = 0; nt < 4; nt++) {
            int col = nb + wn * 32 + nt * 8 + (lane & 3) * 2;
            if (row0 < N_NODES)
                *(float2*)(g_h + (size_t)row0 * HF + col) =
                    make_float2(acc[mt][nt][0], acc[mt][nt][1]);
            if (row0 + 8 < N_NODES)
                *(float2*)(g_h + (size_t)(row0 + 8) * HF + col) =
                    make_float2(acc[mt][nt][2], acc[mt][nt][3]);
            int wc = wn * 32 + nt * 8 + (lane & 3) * 2;   // col within head
            float w0 = wsp[wc], w1 = wsp[wc + 1];
            float u0 = wdp[wc], u1 = wdp[wc + 1];
            s0 += acc[mt][nt][0] * w0 + acc[mt][nt][1] * w1;
            d0 += acc[mt][nt][0] * u0 + acc[mt][nt][1] * u1;
            s1 += acc[mt][nt][2] * w0 + acc[mt][nt][3] * w1;
            d1 += acc[mt][nt][2] * u0 + acc[mt][nt][3] * u1;
        }
        // quad reduce (lanes lane^1, lane^2 share the same row)
#pragma unroll
        for (int o = 1; o <= 2; o <<= 1) {
            s0 += __shfl_xor_sync(0xffffffffu, s0, o);
            s1 += __shfl_xor_sync(0xffffffffu, s1, o);
            d0 += __shfl_xor_sync(0xffffffffu, d0, o);
            d1 += __shfl_xor_sync(0xffffffffu, d1, o);
        }
        if ((lane & 3) == 0) {            // unique writer per (wn, local row)
            int lr = wm * 32 + mt * 16 + (lane >> 2);
            sds[wn][lr] = s0;  sdd[wn][lr] = d0;
            sds[wn][lr + 8] = s1;  sdd[wn][lr + 8] = d1;
        }
    }
    __syncthreads();
    if (tid < 128) {                      // fixed-order sum: deterministic
        int grow = mb + tid;
        if (grow < N_NODES) {
            g_asrc[grow * HEADS + hd] = sds[0][tid] + sds[1][tid];
            g_adst[grow * HEADS + hd] = sdd[0][tid] + sdd[1][tid];
        }
    }
}

// ---------------- CSR build (edge_index is int32: JAX x64 is disabled) ------
__global__ void zero_deg_kernel() {
    int i = blockIdx.x * blockDim.x + threadIdx.x;
    if (i < N_NODES) g_deg[i] = 0;
}

__global__ void hist_kernel(const int* __restrict__ ei) {
    int e = blockIdx.x * blockDim.x + threadIdx.x;
    if (e >= N_EDGES) return;
    int d = ei[N_EDGES + e];
    if ((unsigned)d < N_NODES) atomicAdd(&g_deg[d], 1);
}

__global__ __launch_bounds__(SCAN_CHUNK) void blockred_kernel() {
    __shared__ int sh[SCAN_CHUNK];
    int i = blockIdx.x * SCAN_CHUNK + threadIdx.x;
    int v = (i < N_NODES) ? g_deg[i] : 0;
    sh[threadIdx.x] = v;
    __syncthreads();
#pragma unroll
    for (int off = SCAN_CHUNK / 2; off >= 32; off >>= 1) {
        if (threadIdx.x < off) sh[threadIdx.x] += sh[threadIdx.x + off];
        __syncthreads();
    }
    if (threadIdx.x < 32) {
        int s = sh[threadIdx.x];
#pragma unroll
        for (int o = 16; o; o >>= 1) s += __shfl_xor_sync(0xffffffffu, s, o);
        if (threadIdx.x == 0) g_bsum[blockIdx.x] = s;
    }
}

__global__ __launch_bounds__(128) void scanblk_kernel() {
    __shared__ int sh[128];
    int tid = threadIdx.x;
    int v = (tid < NBLK) ? g_bsum[tid] : 0;
    sh[tid] = v;
    __syncthreads();
#pragma unroll
    for (int off = 1; off < 128; off <<= 1) {
        int t = sh[tid];
        if (tid >= off) t += sh[tid - off];
        __syncthreads();
        sh[tid] = t;
        __syncthreads();
    }
    if (tid < NBLK) g_boff[tid] = sh[tid] - v;     // exclusive
    if (tid == 0) g_off[N_NODES] = sh[NBLK - 1];   // total
}

__global__ __launch_bounds__(SCAN_CHUNK) void offsets_kernel() {
    __shared__ int sh[SCAN_CHUNK];
    int tid = threadIdx.x;
    int i = blockIdx.x * SCAN_CHUNK + tid;
    int v = (i < N_NODES) ? g_deg[i] : 0;
    sh[tid] = v;
    __syncthreads();
#pragma unroll
    for (int off = 1; off < SCAN_CHUNK; off <<= 1) {
        int t = sh[tid];
        if (tid >= off) t += sh[tid - off];
        __syncthreads();
        sh[tid] = t;
        __syncthreads();
    }
    if (i < N_NODES) {
        int excl = g_boff[blockIdx.x] + sh[tid] - v;
        g_off[i] = excl;
        g_cursor[i] = excl;
    }
}

__global__ void scatter_kernel(const int* __restrict__ ei) {
    int e = blockIdx.x * blockDim.x + threadIdx.x;
    if (e >= N_EDGES) return;
    int s = ei[e];
    int d = ei[N_EDGES + e];
    if ((unsigned)d >= N_NODES || (unsigned)s >= N_NODES) return;
    int pos = atomicAdd(&g_cursor[d], 1);
    g_csr[pos] = s;
}

// Canonicalize each segment so fp32 accumulation order is deterministic.
__global__ void sortseg_kernel() {
    int gw = (blockIdx.x * blockDim.x + threadIdx.x) >> 5;
    int lane = threadIdx.x & 31;
    if (gw >= N_NODES) return;
    int lo = g_off[gw], hi = g_off[gw + 1];
    int len = hi - lo;
    if (len < 2) return;
    for (int pass = 0; pass < len; pass++) {
        int start = lo + (pass & 1);
        for (int i = start + 2 * lane; i + 1 < hi; i += 64) {
            int a = g_csr[i], b = g_csr[i + 1];
            if (a > b) { g_csr[i] = b; g_csr[i + 1] = a; }
        }
        __syncwarp();
    }
}

// ------- aggregation: warp per node, 4 heads fused, 2-deep SW pipeline ------
__global__ __launch_bounds__(256) void agg_kernel(const float* __restrict__ bias,
                                                  float* __restrict__ out) {
    int n = (blockIdx.x * blockDim.x + threadIdx.x) >> 5;
    int lane = threadIdx.x & 31;
    if (n >= N_NODES) return;
    int hd = lane >> 3;

    const float4* hrow = (const float4*)(g_h + (size_t)n * HF);
    float4 aA = hrow[lane * 2];
    float4 aB = hrow[lane * 2 + 1];

    float4 adv = *(const float4*)(g_adst + n * HEADS);
    float adn = (hd == 0) ? adv.x : (hd == 1) ? adv.y : (hd == 2) ? adv.z : adv.w;
    float4 asv = *(const float4*)(g_asrc + n * HEADS);
    float e0 = ((hd == 0) ? asv.x : (hd == 1) ? asv.y : (hd == 2) ? asv.z : asv.w) + adn;
    e0 = (e0 > 0.f) ? e0 : NEG_SLOPE * e0;   // self-loop seeds the state
    float m = e0, ssum = 1.0f;

    int lo = g_off[n], hi = g_off[n + 1];

    float4 av, v0, v1;
    if (lo < hi) {
        int s0 = g_csr[lo];
        av = *(const float4*)(g_asrc + s0 * HEADS);
        const float4* hs = (const float4*)(g_h + (size_t)s0 * HF);
        v0 = hs[lane * 2];
        v1 = hs[lane * 2 + 1];
    }
    for (int j = lo; j < hi; j++) {
        float4 cav = av, cv0 = v0, cv1 = v1;
        if (j + 1 < hi) {
            int s1 = g_csr[j + 1];
            av = *(const float4*)(g_asrc + s1 * HEADS);
            const float4* hs = (const float4*)(g_h + (size_t)s1 * HF);
            v0 = hs[lane * 2];
            v1 = hs[lane * 2 + 1];
        }
        float e = ((hd == 0) ? cav.x : (hd == 1) ? cav.y : (hd == 2) ? cav.z : cav.w) + adn;
        e = (e > 0.f) ? e : NEG_SLOPE * e;
        float nm = fmaxf(m, e);
        float corr = __expf(m - nm);
        float w = __expf(e - nm);
        ssum = ssum * corr + w;
        aA.x = aA.x * corr + w * cv0.x;  aA.y = aA.y * corr + w * cv0.y;
        aA.z = aA.z * corr + w * cv0.z;  aA.w = aA.w * corr + w * cv0.w;
        aB.x = aB.x * corr + w * cv1.x;  aB.y = aB.y * corr + w * cv1.y;
        aB.z = aB.z * corr + w * cv1.z;  aB.w = aB.w * corr + w * cv1.w;
        m = nm;
    }

    float inv = 1.0f / ssum;
    float4 b0 = *(const float4*)(bias + lane * 8);
    float4 b1 = *(const float4*)(bias + lane * 8 + 4);
    float4* orow = (float4*)(out + (size_t)n * HF);
    orow[lane * 2]     = make_float4(aA.x * inv + b0.x, aA.y * inv + b0.y,
                                     aA.z * inv + b0.z, aA.w * inv + b0.w);
    orow[lane * 2 + 1] = make_float4(aB.x * inv + b1.x, aB.y * inv + b1.y,
                                     aB.z * inv + b1.z, aB.w * inv + b1.w);
}

// ---------------- launch ----------------------------------------------------
extern "C" void kernel_launch(void* const* d_in, const int* in_sizes, int n_in,
                              void* d_out, int out_size) {
    const float* x     = (const float*)d_in[0];
    const int*   ei    = (const int*)d_in[1];       // int32: JAX x64 disabled
    const float* W     = (const float*)d_in[2];
    const float* att_s = (const float*)d_in[3];
    const float* att_d = (const float*)d_in[4];
    const float* bias  = (const float*)d_in[5];
    float*       out   = (float*)d_out;
    (void)in_sizes; (void)n_in; (void)out_size;

    wsplit_kernel<<<(IN_F * HF + 255) / 256, 256>>>(W);
    xsplit_kernel<<<(N_NODES * 32 + 255) / 256, 256>>>(x);
    gemm_bf16_kernel<<<dim3((N_NODES + 127) / 128, HF / 64), 256>>>(att_s, att_d);
    zero_deg_kernel<<<(N_NODES + 255) / 256, 256>>>();
    hist_kernel<<<(N_EDGES + 255) / 256, 256>>>(ei);
    blockred_kernel<<<NBLK, SCAN_CHUNK>>>();
    scanblk_kernel<<<1, 128>>>();
    offsets_kernel<<<NBLK, SCAN_CHUNK>>>();
    scatter_kernel<<<(N_EDGES + 255) / 256, 256>>>(ei);
    sortseg_kernel<<<(N_NODES * 32 + 255) / 256, 256>>>();
    agg_kernel<<<(N_NODES * 32 + 255) / 256, 256>>>(bias, out);
}

// round 13
// speedup vs baseline: 1.0035x; 1.0035x over previous
#include <cuda_runtime.h>
#include <cuda_bf16.h>
#include <cstdint>

#define N_NODES 50000
#define N_EDGES 800000
#define IN_F 256
#define HEADS 4
#define OUT_F 64
#define HF 256            // HEADS * OUT_F
#define NEG_SLOPE 0.2f

#define SCAN_CHUNK 512
#define NBLK ((N_NODES + SCAN_CHUNK - 1) / SCAN_CHUNK)   // 98

// ---------------- scratch (static device allocations; no cudaMalloc) --------
__device__ float g_h[(size_t)N_NODES * HF];      // 51.2 MB  projected features
__device__ __nv_bfloat16 g_xhi[(size_t)N_NODES * IN_F];   // 25.6 MB
__device__ __nv_bfloat16 g_xlo[(size_t)N_NODES * IN_F];   // 25.6 MB
__device__ __nv_bfloat16 g_Whi[IN_F * HF];
__device__ __nv_bfloat16 g_Wlo[IN_F * HF];
__device__ float g_asrc[N_NODES * HEADS];
__device__ float g_adst[N_NODES * HEADS];
__device__ int   g_deg[N_NODES];
__device__ int   g_off[N_NODES + 1];
__device__ int   g_cursor[N_NODES];
__device__ int   g_csr[N_EDGES];                 // src ids grouped by dst
__device__ int   g_bsum[NBLK];
__device__ int   g_boff[NBLK];

// ---------------- split kernels: v -> bf16 hi + bf16 residual ---------------
__global__ void wsplit_kernel(const float* __restrict__ W) {
    int i = blockIdx.x * blockDim.x + threadIdx.x;
    if (i >= IN_F * HF) return;
    float w = W[i];
    __nv_bfloat16 hi = __float2bfloat16(w);
    __nv_bfloat16 lo = __float2bfloat16(w - __bfloat162float(hi));
    g_Whi[i] = hi;
    g_Wlo[i] = lo;
}

__global__ __launch_bounds__(256) void xsplit_kernel(const float* __restrict__ x) {
    // warp per node; lane owns 8 consecutive floats
    int n = (blockIdx.x * blockDim.x + threadIdx.x) >> 5;
    int lane = threadIdx.x & 31;
    if (n >= N_NODES) return;
    const float4* xr = (const float4*)(x + (size_t)n * IN_F) + lane * 2;
    float4 xa = xr[0], xb = xr[1];
    float xs[8] = {xa.x, xa.y, xa.z, xa.w, xb.x, xb.y, xb.z, xb.w};
    union { __nv_bfloat16 b[8]; uint4 u; } H, L;
#pragma unroll
    for (int i = 0; i < 8; i++) {
        H.b[i] = __float2bfloat16(xs[i]);
        L.b[i] = __float2bfloat16(xs[i] - __bfloat162float(H.b[i]));
    }
    *(uint4*)(g_xhi + (size_t)n * IN_F + lane * 8) = H.u;
    *(uint4*)(g_xlo + (size_t)n * IN_F + lane * 8) = L.u;
}

// ---------------- GEMM: g_h = x @ W via 3 bf16 tensor-core passes -----------
// hi*hi + hi*lo + lo*hi  (lo*lo dropped, ~2^-16 relative)
// blockIdx.y = head; fused a_src/a_dst epilogue (deterministic, no atomics).
#define ASTRIDE 40   // bf16 elements per A smem row (80B, conflict-free ldmatrix)
#define BSTRIDE 72   // bf16 elements per B smem row (144B)

__device__ __forceinline__ void ldsm4(uint32_t* r, const __nv_bfloat16* p) {
    unsigned a = (unsigned)__cvta_generic_to_shared(p);
    asm volatile("ldmatrix.sync.aligned.m8n8.x4.shared.b16 {%0,%1,%2,%3}, [%4];"
                 : "=r"(r[0]), "=r"(r[1]), "=r"(r[2]), "=r"(r[3]) : "r"(a));
}
__device__ __forceinline__ void ldsm4t(uint32_t* r, const __nv_bfloat16* p) {
    unsigned a = (unsigned)__cvta_generic_to_shared(p);
    asm volatile("ldmatrix.sync.aligned.m8n8.x4.trans.shared.b16 {%0,%1,%2,%3}, [%4];"
                 : "=r"(r[0]), "=r"(r[1]), "=r"(r[2]), "=r"(r[3]) : "r"(a));
}
__device__ __forceinline__ void mma16816(float* c, const uint32_t* a, uint32_t b0, uint32_t b1) {
    asm volatile("mma.sync.aligned.m16n8k16.row.col.f32.bf16.bf16.f32 "
                 "{%0,%1,%2,%3}, {%4,%5,%6,%7}, {%8,%9}, {%0,%1,%2,%3};"
                 : "+f"(c[0]), "+f"(c[1]), "+f"(c[2]), "+f"(c[3])
                 : "r"(a[0]), "r"(a[1]), "r"(a[2]), "r"(a[3]), "r"(b0), "r"(b1));
}

__global__ __launch_bounds__(256) void gemm_bf16_kernel(const float* __restrict__ att_s,
                                                        const float* __restrict__ att_d) {
    __shared__ __align__(16) __nv_bfloat16 sA[128 * ASTRIDE];  // 10240 B
    __shared__ __align__(16) __nv_bfloat16 sB[32 * BSTRIDE];   //  4608 B
    __shared__ float sds[2][128];   // per-(wn,row) a_src partials
    __shared__ float sdd[2][128];   // per-(wn,row) a_dst partials

    const int tid = threadIdx.x;
    const int lane = tid & 31;
    const int wid = tid >> 5;
    const int wm = wid & 3;        // 4 M-warps of 32 rows
    const int wn = wid >> 2;       // 2 N-warps of 32 cols
    const int mb = blockIdx.x * 128;
    const int hd = blockIdx.y;     // head; nb = hd*64
    const int nb = hd * 64;
    const int lrow = lane & 15;
    const int lcol8 = (lane >> 4) << 3;   // 0 or 8 (bf16 elements)

    float acc[2][4][4];
#pragma unroll
    for (int i = 0; i < 2; i++)
#pragma unroll
        for (int j = 0; j < 4; j++)
#pragma unroll
            for (int k = 0; k < 4; k++) acc[i][j][k] = 0.f;

#pragma unroll 1
    for (int seg = 0; seg < 3; seg++) {
        const __nv_bfloat16* Ag = (seg == 2) ? g_xlo : g_xhi;
        const __nv_bfloat16* Bg = (seg == 1) ? g_Wlo : g_Whi;
#pragma unroll 1
        for (int kt = 0; kt < IN_F; kt += 32) {
            // A tile: 128 rows x 32 bf16 = 512 x 16B chunks, 2 per thread
#pragma unroll
            for (int i = 0; i < 2; i++) {
                int c = tid + i * 256;
                int r = c >> 2, c16 = c & 3;
                int grow = mb + r;
                uint4 v = make_uint4(0, 0, 0, 0);
                if (grow < N_NODES)
                    v = *(const uint4*)(Ag + (size_t)grow * IN_F + kt + c16 * 8);
                *(uint4*)(sA + r * ASTRIDE + c16 * 8) = v;
            }
            // B tile: 32 rows x 64 bf16 = 256 x 16B chunks, 1 per thread
            {
                int r = tid >> 3, c16 = tid & 7;
                uint4 v = *(const uint4*)(Bg + (size_t)(kt + r) * HF + nb + c16 * 8);
                *(uint4*)(sB + r * BSTRIDE + c16 * 8) = v;
            }
            __syncthreads();

            uint32_t a[2][2][4], b[2][2][4];
#pragma unroll
            for (int mt = 0; mt < 2; mt++)
#pragma unroll
                for (int kc = 0; kc < 2; kc++)
                    ldsm4(a[mt][kc],
                          sA + (wm * 32 + mt * 16 + lrow) * ASTRIDE + kc * 16 + lcol8);
#pragma unroll
            for (int kc = 0; kc < 2; kc++)
#pragma unroll
                for (int nt2 = 0; nt2 < 2; nt2++)
                    ldsm4t(b[kc][nt2],
                           sB + (kc * 16 + lrow) * BSTRIDE + wn * 32 + nt2 * 16 + lcol8);
#pragma unroll
            for (int mt = 0; mt < 2; mt++)
#pragma unroll
                for (int nt = 0; nt < 4; nt++)
#pragma unroll
                    for (int kc = 0; kc < 2; kc++) {
                        uint32_t* bb = &b[kc][nt >> 1][(nt & 1) * 2];
                        mma16816(acc[mt][nt], a[mt][kc], bb[0], bb[1]);
                    }
            __syncthreads();
        }
    }

    // ---- epilogue: store g_h + fused attention dots ----
    const float* wsp = att_s + hd * OUT_F;
    const float* wdp = att_d + hd * OUT_F;

#pragma unroll
    for (int mt = 0; mt < 2; mt++) {
        int row0 = mb + wm * 32 + mt * 16 + (lane >> 2);
        float s0 = 0.f, s1 = 0.f, d0 = 0.f, d1 = 0.f;
#pragma unroll
        for (int nt = 0; nt < 4; nt++) {
            int col = nb + wn * 32 + nt * 8 + (lane & 3) * 2;
            if (row0 < N_NODES)
                *(float2*)(g_h + (size_t)row0 * HF + col) =
                    make_float2(acc[mt][nt][0], acc[mt][nt][1]);
            if (row0 + 8 < N_NODES)
                *(float2*)(g_h + (size_t)(row0 + 8) * HF + col) =
                    make_float2(acc[mt][nt][2], acc[mt][nt][3]);
            int wc = wn * 32 + nt * 8 + (lane & 3) * 2;   // col within head
            float w0 = wsp[wc], w1 = wsp[wc + 1];
            float u0 = wdp[wc], u1 = wdp[wc + 1];
            s0 += acc[mt][nt][0] * w0 + acc[mt][nt][1] * w1;
            d0 += acc[mt][nt][0] * u0 + acc[mt][nt][1] * u1;
            s1 += acc[mt][nt][2] * w0 + acc[mt][nt][3] * w1;
            d1 += acc[mt][nt][2] * u0 + acc[mt][nt][3] * u1;
        }
        // quad reduce (lanes lane^1, lane^2 share the same row)
#pragma unroll
        for (int o = 1; o <= 2; o <<= 1) {
            s0 += __shfl_xor_sync(0xffffffffu, s0, o);
            s1 += __shfl_xor_sync(0xffffffffu, s1, o);
            d0 += __shfl_xor_sync(0xffffffffu, d0, o);
            d1 += __shfl_xor_sync(0xffffffffu, d1, o);
        }
        if ((lane & 3) == 0) {            // unique writer per (wn, local row)
            int lr = wm * 32 + mt * 16 + (lane >> 2);
            sds[wn][lr] = s0;  sdd[wn][lr] = d0;
            sds[wn][lr + 8] = s1;  sdd[wn][lr + 8] = d1;
        }
    }
    __syncthreads();
    if (tid < 128) {                      // fixed-order sum: deterministic
        int grow = mb + tid;
        if (grow < N_NODES) {
            g_asrc[grow * HEADS + hd] = sds[0][tid] + sds[1][tid];
            g_adst[grow * HEADS + hd] = sdd[0][tid] + sdd[1][tid];
        }
    }
}

// ---------------- CSR build (edge_index is int32: JAX x64 is disabled) ------
__global__ void zero_deg_kernel() {
    int i = blockIdx.x * blockDim.x + threadIdx.x;
    if (i < N_NODES) g_deg[i] = 0;
}

__global__ void hist_kernel(const int* __restrict__ ei) {
    int e = blockIdx.x * blockDim.x + threadIdx.x;
    if (e >= N_EDGES) return;
    int d = ei[N_EDGES + e];
    if ((unsigned)d < N_NODES) atomicAdd(&g_deg[d], 1);
}

__global__ __launch_bounds__(SCAN_CHUNK) void blockred_kernel() {
    __shared__ int sh[SCAN_CHUNK];
    int i = blockIdx.x * SCAN_CHUNK + threadIdx.x;
    int v = (i < N_NODES) ? g_deg[i] : 0;
    sh[threadIdx.x] = v;
    __syncthreads();
#pragma unroll
    for (int off = SCAN_CHUNK / 2; off >= 32; off >>= 1) {
        if (threadIdx.x < off) sh[threadIdx.x] += sh[threadIdx.x + off];
        __syncthreads();
    }
    if (threadIdx.x < 32) {
        int s = sh[threadIdx.x];
#pragma unroll
        for (int o = 16; o; o >>= 1) s += __shfl_xor_sync(0xffffffffu, s, o);
        if (threadIdx.x == 0) g_bsum[blockIdx.x] = s;
    }
}

__global__ __launch_bounds__(128) void scanblk_kernel() {
    __shared__ int sh[128];
    int tid = threadIdx.x;
    int v = (tid < NBLK) ? g_bsum[tid] : 0;
    sh[tid] = v;
    __syncthreads();
#pragma unroll
    for (int off = 1; off < 128; off <<= 1) {
        int t = sh[tid];
        if (tid >= off) t += sh[tid - off];
        __syncthreads();
        sh[tid] = t;
        __syncthreads();
    }
    if (tid < NBLK) g_boff[tid] = sh[tid] - v;     // exclusive
    if (tid == 0) g_off[N_NODES] = sh[NBLK - 1];   // total
}

__global__ __launch_bounds__(SCAN_CHUNK) void offsets_kernel() {
    __shared__ int sh[SCAN_CHUNK];
    int tid = threadIdx.x;
    int i = blockIdx.x * SCAN_CHUNK + tid;
    int v = (i < N_NODES) ? g_deg[i] : 0;
    sh[tid] = v;
    __syncthreads();
#pragma unroll
    for (int off = 1; off < SCAN_CHUNK; off <<= 1) {
        int t = sh[tid];
        if (tid >= off) t += sh[tid - off];
        __syncthreads();
        sh[tid] = t;
        __syncthreads();
    }
    if (i < N_NODES) {
        int excl = g_boff[blockIdx.x] + sh[tid] - v;
        g_off[i] = excl;
        g_cursor[i] = excl;
    }
}

__global__ void scatter_kernel(const int* __restrict__ ei) {
    int e = blockIdx.x * blockDim.x + threadIdx.x;
    if (e >= N_EDGES) return;
    int s = ei[e];
    int d = ei[N_EDGES + e];
    if ((unsigned)d >= N_NODES || (unsigned)s >= N_NODES) return;
    int pos = atomicAdd(&g_cursor[d], 1);
    g_csr[pos] = s;
}

// Canonicalize each segment so fp32 accumulation order is deterministic.
__global__ void sortseg_kernel() {
    int gw = (blockIdx.x * blockDim.x + threadIdx.x) >> 5;
    int lane = threadIdx.x & 31;
    if (gw >= N_NODES) return;
    int lo = g_off[gw], hi = g_off[gw + 1];
    int len = hi - lo;
    if (len < 2) return;
    for (int pass = 0; pass < len; pass++) {
        int start = lo + (pass & 1);
        for (int i = start + 2 * lane; i + 1 < hi; i += 64) {
            int a = g_csr[i], b = g_csr[i + 1];
            if (a > b) { g_csr[i] = b; g_csr[i + 1] = a; }
        }
        __syncwarp();
    }
}

// ------- aggregation: warp per node, 4 heads fused, 2-deep SW pipeline ------
__global__ __launch_bounds__(256) void agg_kernel(const float* __restrict__ bias,
                                                  float* __restrict__ out) {
    int n = (blockIdx.x * blockDim.x + threadIdx.x) >> 5;
    int lane = threadIdx.x & 31;
    if (n >= N_NODES) return;
    int hd = lane >> 3;

    const float4* hrow = (const float4*)(g_h + (size_t)n * HF);
    float4 aA = hrow[lane * 2];
    float4 aB = hrow[lane * 2 + 1];

    float4 adv = *(const float4*)(g_adst + n * HEADS);
    float adn = (hd == 0) ? adv.x : (hd == 1) ? adv.y : (hd == 2) ? adv.z : adv.w;
    float4 asv = *(const float4*)(g_asrc + n * HEADS);
    float e0 = ((hd == 0) ? asv.x : (hd == 1) ? asv.y : (hd == 2) ? asv.z : asv.w) + adn;
    e0 = (e0 > 0.f) ? e0 : NEG_SLOPE * e0;   // self-loop seeds the state
    float m = e0, ssum = 1.0f;

    int lo = g_off[n], hi = g_off[n + 1];

    float4 av, v0, v1;
    if (lo < hi) {
        int s0 = g_csr[lo];
        av = *(const float4*)(g_asrc + s0 * HEADS);
        const float4* hs = (const float4*)(g_h + (size_t)s0 * HF);
        v0 = hs[lane * 2];
        v1 = hs[lane * 2 + 1];
    }
    for (int j = lo; j < hi; j++) {
        float4 cav = av, cv0 = v0, cv1 = v1;
        if (j + 1 < hi) {
            int s1 = g_csr[j + 1];
            av = *(const float4*)(g_asrc + s1 * HEADS);
            const float4* hs = (const float4*)(g_h + (size_t)s1 * HF);
            v0 = hs[lane * 2];
            v1 = hs[lane * 2 + 1];
        }
        float e = ((hd == 0) ? cav.x : (hd == 1) ? cav.y : (hd == 2) ? cav.z : cav.w) + adn;
        e = (e > 0.f) ? e : NEG_SLOPE * e;
        float nm = fmaxf(m, e);
        float corr = __expf(m - nm);
        float w = __expf(e - nm);
        ssum = ssum * corr + w;
        aA.x = aA.x * corr + w * cv0.x;  aA.y = aA.y * corr + w * cv0.y;
        aA.z = aA.z * corr + w * cv0.z;  aA.w = aA.w * corr + w * cv0.w;
        aB.x = aB.x * corr + w * cv1.x;  aB.y = aB.y * corr + w * cv1.y;
        aB.z = aB.z * corr + w * cv1.z;  aB.w = aB.w * corr + w * cv1.w;
        m = nm;
    }

    float inv = 1.0f / ssum;
    float4 b0 = *(const float4*)(bias + lane * 8);
    float4 b1 = *(const float4*)(bias + lane * 8 + 4);
    float4* orow = (float4*)(out + (size_t)n * HF);
    orow[lane * 2]     = make_float4(aA.x * inv + b0.x, aA.y * inv + b0.y,
                                     aA.z * inv + b0.z, aA.w * inv + b0.w);
    orow[lane * 2 + 1] = make_float4(aB.x * inv + b1.x, aB.y * inv + b1.y,
                                     aB.z * inv + b1.z, aB.w * inv + b1.w);
}

// ---------------- launch ----------------------------------------------------
extern "C" void kernel_launch(void* const* d_in, const int* in_sizes, int n_in,
                              void* d_out, int out_size) {
    const float* x     = (const float*)d_in[0];
    const int*   ei    = (const int*)d_in[1];       // int32: JAX x64 disabled
    const float* W     = (const float*)d_in[2];
    const float* att_s = (const float*)d_in[3];
    const float* att_d = (const float*)d_in[4];
    const float* bias  = (const float*)d_in[5];
    float*       out   = (float*)d_out;
    (void)in_sizes; (void)n_in; (void)out_size;

    wsplit_kernel<<<(IN_F * HF + 255) / 256, 256>>>(W);
    xsplit_kernel<<<(N_NODES * 32 + 255) / 256, 256>>>(x);
    gemm_bf16_kernel<<<dim3((N_NODES + 127) / 128, HF / 64), 256>>>(att_s, att_d);
    zero_deg_kernel<<<(N_NODES + 255) / 256, 256>>>();
    hist_kernel<<<(N_EDGES + 255) / 256, 256>>>(ei);
    blockred_kernel<<<NBLK, SCAN_CHUNK>>>();
    scanblk_kernel<<<1, 128>>>();
    offsets_kernel<<<NBLK, SCAN_CHUNK>>>();
    scatter_kernel<<<(N_EDGES + 255) / 256, 256>>>(ei);
    sortseg_kernel<<<(N_NODES * 32 + 255) / 256, 256>>>();
    agg_kernel<<<(N_NODES * 32 + 255) / 256, 256>>>(bias, out);
}

// round 14
// speedup vs baseline: 1.1717x; 1.1676x over previous
#include <cuda_runtime.h>
#include <cuda_bf16.h>
#include <cstdint>

#define N_NODES 50000
#define N_EDGES 800000
#define IN_F 256
#define HEADS 4
#define OUT_F 64
#define HF 256            // HEADS * OUT_F
#define NEG_SLOPE 0.2f

#define SCAN_CHUNK 512
#define NBLK ((N_NODES + SCAN_CHUNK - 1) / SCAN_CHUNK)   // 98

// ---------------- scratch (static device allocations; no cudaMalloc) --------
__device__ float g_h[(size_t)N_NODES * HF];      // 51.2 MB  projected features
__device__ __nv_bfloat16 g_Whi[IN_F * HF];
__device__ __nv_bfloat16 g_Wlo[IN_F * HF];
__device__ float g_asrc[N_NODES * HEADS];
__device__ float g_adst[N_NODES * HEADS];
__device__ int   g_deg[N_NODES];
__device__ int   g_off[N_NODES + 1];
__device__ int   g_cursor[N_NODES];
__device__ int   g_csr[N_EDGES];                 // src ids grouped by dst
__device__ int   g_bsum[NBLK];
__device__ int   g_boff[NBLK];

// ---------------- W split: fp32 -> bf16 hi + bf16 residual (tiny) -----------
__global__ void wsplit_kernel(const float* __restrict__ W) {
    int i = blockIdx.x * blockDim.x + threadIdx.x;
    if (i >= IN_F * HF) return;
    float w = W[i];
    __nv_bfloat16 hi = __float2bfloat16(w);
    __nv_bfloat16 lo = __float2bfloat16(w - __bfloat162float(hi));
    g_Whi[i] = hi;
    g_Wlo[i] = lo;
}

// ---------------- GEMM: g_h = x @ W, split-bf16 on tensor cores -------------
// Per k-tile: load fp32 x ONCE, split to hi/lo in registers, stage smem,
// then mma hi*hi + hi*lo + lo*hi (lo*lo dropped, ~2^-16 relative).
// blockIdx.y = head; fused a_src/a_dst epilogue (deterministic, no atomics).
#define ASTRIDE 40   // bf16 elements per A smem row (80B, conflict-free ldmatrix)
#define BSTRIDE 72   // bf16 elements per B smem row (144B)

__device__ __forceinline__ void ldsm4(uint32_t* r, const __nv_bfloat16* p) {
    unsigned a = (unsigned)__cvta_generic_to_shared(p);
    asm volatile("ldmatrix.sync.aligned.m8n8.x4.shared.b16 {%0,%1,%2,%3}, [%4];"
                 : "=r"(r[0]), "=r"(r[1]), "=r"(r[2]), "=r"(r[3]) : "r"(a));
}
__device__ __forceinline__ void ldsm4t(uint32_t* r, const __nv_bfloat16* p) {
    unsigned a = (unsigned)__cvta_generic_to_shared(p);
    asm volatile("ldmatrix.sync.aligned.m8n8.x4.trans.shared.b16 {%0,%1,%2,%3}, [%4];"
                 : "=r"(r[0]), "=r"(r[1]), "=r"(r[2]), "=r"(r[3]) : "r"(a));
}
__device__ __forceinline__ void mma16816(float* c, const uint32_t* a, uint32_t b0, uint32_t b1) {
    asm volatile("mma.sync.aligned.m16n8k16.row.col.f32.bf16.bf16.f32 "
                 "{%0,%1,%2,%3}, {%4,%5,%6,%7}, {%8,%9}, {%0,%1,%2,%3};"
                 : "+f"(c[0]), "+f"(c[1]), "+f"(c[2]), "+f"(c[3])
                 : "r"(a[0]), "r"(a[1]), "r"(a[2]), "r"(a[3]), "r"(b0), "r"(b1));
}

__global__ __launch_bounds__(256) void gemm_bf16_kernel(const float* __restrict__ x,
                                                        const float* __restrict__ att_s,
                                                        const float* __restrict__ att_d) {
    __shared__ __align__(16) __nv_bfloat16 sAhi[128 * ASTRIDE];  // 10240 B
    __shared__ __align__(16) __nv_bfloat16 sAlo[128 * ASTRIDE];  // 10240 B
    __shared__ __align__(16) __nv_bfloat16 sBhi[32 * BSTRIDE];   //  4608 B
    __shared__ __align__(16) __nv_bfloat16 sBlo[32 * BSTRIDE];   //  4608 B
    __shared__ float sds[2][128];   // per-(wn,row) a_src partials
    __shared__ float sdd[2][128];   // per-(wn,row) a_dst partials

    const int tid = threadIdx.x;
    const int lane = tid & 31;
    const int wid = tid >> 5;
    const int wm = wid & 3;        // 4 M-warps of 32 rows
    const int wn = wid >> 2;       // 2 N-warps of 32 cols
    const int mb = blockIdx.x * 128;
    const int hd = blockIdx.y;     // head; nb = hd*64
    const int nb = hd * 64;
    const int lrow = lane & 15;
    const int lcol8 = (lane >> 4) << 3;   // 0 or 8 (bf16 elements)

    float acc[2][4][4];
#pragma unroll
    for (int i = 0; i < 2; i++)
#pragma unroll
        for (int j = 0; j < 4; j++)
#pragma unroll
            for (int k = 0; k < 4; k++) acc[i][j][k] = 0.f;

#pragma unroll 1
    for (int kt = 0; kt < IN_F; kt += 32) {
        // A tile: 128 rows x 32 fp32, loaded once and split in registers.
        // 512 tasks of 8 floats; 2 per thread.
#pragma unroll
        for (int i = 0; i < 2; i++) {
            int t = tid + i * 256;
            int r = t >> 2, ch = t & 3;           // row, 8-float chunk
            int grow = mb + r;
            float4 xa = make_float4(0.f, 0.f, 0.f, 0.f);
            float4 xb = make_float4(0.f, 0.f, 0.f, 0.f);
            if (grow < N_NODES) {
                const float4* xp = (const float4*)(x + (size_t)grow * IN_F + kt + ch * 8);
                xa = xp[0]; xb = xp[1];
            }
            float xs[8] = {xa.x, xa.y, xa.z, xa.w, xb.x, xb.y, xb.z, xb.w};
            union { __nv_bfloat16 b[8]; uint4 u; } H, L;
#pragma unroll
            for (int q = 0; q < 8; q++) {
                H.b[q] = __float2bfloat16(xs[q]);
                L.b[q] = __float2bfloat16(xs[q] - __bfloat162float(H.b[q]));
            }
            *(uint4*)(sAhi + r * ASTRIDE + ch * 8) = H.u;
            *(uint4*)(sAlo + r * ASTRIDE + ch * 8) = L.u;
        }
        // B tiles: 32 rows x 64 bf16 each, 1 uint4 per thread per tile
        {
            int r = tid >> 3, c16 = tid & 7;
            size_t go = (size_t)(kt + r) * HF + nb + c16 * 8;
            *(uint4*)(sBhi + r * BSTRIDE + c16 * 8) = *(const uint4*)(g_Whi + go);
            *(uint4*)(sBlo + r * BSTRIDE + c16 * 8) = *(const uint4*)(g_Wlo + go);
        }
        __syncthreads();

        uint32_t ah[2][2][4], al[2][2][4], bh[2][2][4], bl[2][2][4];
#pragma unroll
        for (int mt = 0; mt < 2; mt++)
#pragma unroll
            for (int kc = 0; kc < 2; kc++) {
                int off = (wm * 32 + mt * 16 + lrow) * ASTRIDE + kc * 16 + lcol8;
                ldsm4(ah[mt][kc], sAhi + off);
                ldsm4(al[mt][kc], sAlo + off);
            }
#pragma unroll
        for (int kc = 0; kc < 2; kc++)
#pragma unroll
            for (int nt2 = 0; nt2 < 2; nt2++) {
                int off = (kc * 16 + lrow) * BSTRIDE + wn * 32 + nt2 * 16 + lcol8;
                ldsm4t(bh[kc][nt2], sBhi + off);
                ldsm4t(bl[kc][nt2], sBlo + off);
            }
#pragma unroll
        for (int mt = 0; mt < 2; mt++)
#pragma unroll
            for (int nt = 0; nt < 4; nt++)
#pragma unroll
                for (int kc = 0; kc < 2; kc++) {
                    uint32_t* bhp = &bh[kc][nt >> 1][(nt & 1) * 2];
                    uint32_t* blp = &bl[kc][nt >> 1][(nt & 1) * 2];
                    mma16816(acc[mt][nt], ah[mt][kc], bhp[0], bhp[1]);  // hi*hi
                    mma16816(acc[mt][nt], ah[mt][kc], blp[0], blp[1]);  // hi*lo
                    mma16816(acc[mt][nt], al[mt][kc], bhp[0], bhp[1]);  // lo*hi
                }
        __syncthreads();
    }

    // ---- epilogue: store g_h + fused attention dots ----
    const float* wsp = att_s + hd * OUT_F;
    const float* wdp = att_d + hd * OUT_F;

#pragma unroll
    for (int mt = 0; mt < 2; mt++) {
        int row0 = mb + wm * 32 + mt * 16 + (lane >> 2);
        float s0 = 0.f, s1 = 0.f, d0 = 0.f, d1 = 0.f;
#pragma unroll
        for (int nt = 0; nt < 4; nt++) {
            int col = nb + wn * 32 + nt * 8 + (lane & 3) * 2;
            if (row0 < N_NODES)
                *(float2*)(g_h + (size_t)row0 * HF + col) =
                    make_float2(acc[mt][nt][0], acc[mt][nt][1]);
            if (row0 + 8 < N_NODES)
                *(float2*)(g_h + (size_t)(row0 + 8) * HF + col) =
                    make_float2(acc[mt][nt][2], acc[mt][nt][3]);
            int wc = wn * 32 + nt * 8 + (lane & 3) * 2;   // col within head
            float w0 = wsp[wc], w1 = wsp[wc + 1];
            float u0 = wdp[wc], u1 = wdp[wc + 1];
            s0 += acc[mt][nt][0] * w0 + acc[mt][nt][1] * w1;
            d0 += acc[mt][nt][0] * u0 + acc[mt][nt][1] * u1;
            s1 += acc[mt][nt][2] * w0 + acc[mt][nt][3] * w1;
            d1 += acc[mt][nt][2] * u0 + acc[mt][nt][3] * u1;
        }
#pragma unroll
        for (int o = 1; o <= 2; o <<= 1) {
            s0 += __shfl_xor_sync(0xffffffffu, s0, o);
            s1 += __shfl_xor_sync(0xffffffffu, s1, o);
            d0 += __shfl_xor_sync(0xffffffffu, d0, o);
            d1 += __shfl_xor_sync(0xffffffffu, d1, o);
        }
        if ((lane & 3) == 0) {            // unique writer per (wn, local row)
            int lr = wm * 32 + mt * 16 + (lane >> 2);
            sds[wn][lr] = s0;  sdd[wn][lr] = d0;
            sds[wn][lr + 8] = s1;  sdd[wn][lr + 8] = d1;
        }
    }
    __syncthreads();
    if (tid < 128) {                      // fixed-order sum: deterministic
        int grow = mb + tid;
        if (grow < N_NODES) {
            g_asrc[grow * HEADS + hd] = sds[0][tid] + sds[1][tid];
            g_adst[grow * HEADS + hd] = sdd[0][tid] + sdd[1][tid];
        }
    }
}

// ---------------- CSR build (edge_index is int32: JAX x64 is disabled) ------
__global__ void zero_deg_kernel() {
    int i = blockIdx.x * blockDim.x + threadIdx.x;
    if (i < N_NODES) g_deg[i] = 0;
}

__global__ void hist_kernel(const int* __restrict__ ei) {
    int e = blockIdx.x * blockDim.x + threadIdx.x;
    if (e >= N_EDGES) return;
    int d = ei[N_EDGES + e];
    if ((unsigned)d < N_NODES) atomicAdd(&g_deg[d], 1);
}

__global__ __launch_bounds__(SCAN_CHUNK) void blockred_kernel() {
    __shared__ int sh[SCAN_CHUNK];
    int i = blockIdx.x * SCAN_CHUNK + threadIdx.x;
    int v = (i < N_NODES) ? g_deg[i] : 0;
    sh[threadIdx.x] = v;
    __syncthreads();
#pragma unroll
    for (int off = SCAN_CHUNK / 2; off >= 32; off >>= 1) {
        if (threadIdx.x < off) sh[threadIdx.x] += sh[threadIdx.x + off];
        __syncthreads();
    }
    if (threadIdx.x < 32) {
        int s = sh[threadIdx.x];
#pragma unroll
        for (int o = 16; o; o >>= 1) s += __shfl_xor_sync(0xffffffffu, s, o);
        if (threadIdx.x == 0) g_bsum[blockIdx.x] = s;
    }
}

__global__ __launch_bounds__(128) void scanblk_kernel() {
    __shared__ int sh[128];
    int tid = threadIdx.x;
    int v = (tid < NBLK) ? g_bsum[tid] : 0;
    sh[tid] = v;
    __syncthreads();
#pragma unroll
    for (int off = 1; off < 128; off <<= 1) {
        int t = sh[tid];
        if (tid >= off) t += sh[tid - off];
        __syncthreads();
        sh[tid] = t;
        __syncthreads();
    }
    if (tid < NBLK) g_boff[tid] = sh[tid] - v;     // exclusive
    if (tid == 0) g_off[N_NODES] = sh[NBLK - 1];   // total
}

__global__ __launch_bounds__(SCAN_CHUNK) void offsets_kernel() {
    __shared__ int sh[SCAN_CHUNK];
    int tid = threadIdx.x;
    int i = blockIdx.x * SCAN_CHUNK + tid;
    int v = (i < N_NODES) ? g_deg[i] : 0;
    sh[tid] = v;
    __syncthreads();
#pragma unroll
    for (int off = 1; off < SCAN_CHUNK; off <<= 1) {
        int t = sh[tid];
        if (tid >= off) t += sh[tid - off];
        __syncthreads();
        sh[tid] = t;
        __syncthreads();
    }
    if (i < N_NODES) {
        int excl = g_boff[blockIdx.x] + sh[tid] - v;
        g_off[i] = excl;
        g_cursor[i] = excl;
    }
}

__global__ void scatter_kernel(const int* __restrict__ ei) {
    int e = blockIdx.x * blockDim.x + threadIdx.x;
    if (e >= N_EDGES) return;
    int s = ei[e];
    int d = ei[N_EDGES + e];
    if ((unsigned)d >= N_NODES || (unsigned)s >= N_NODES) return;
    int pos = atomicAdd(&g_cursor[d], 1);
    g_csr[pos] = s;
}

// Canonicalize each segment so fp32 accumulation order is deterministic.
__global__ void sortseg_kernel() {
    int gw = (blockIdx.x * blockDim.x + threadIdx.x) >> 5;
    int lane = threadIdx.x & 31;
    if (gw >= N_NODES) return;
    int lo = g_off[gw], hi = g_off[gw + 1];
    int len = hi - lo;
    if (len < 2) return;
    for (int pass = 0; pass < len; pass++) {
        int start = lo + (pass & 1);
        for (int i = start + 2 * lane; i + 1 < hi; i += 64) {
            int a = g_csr[i], b = g_csr[i + 1];
            if (a > b) { g_csr[i] = b; g_csr[i + 1] = a; }
        }
        __syncwarp();
    }
}

// ------- aggregation: warp per node, 4 heads fused, 2-deep SW pipeline ------
__global__ __launch_bounds__(256) void agg_kernel(const float* __restrict__ bias,
                                                  float* __restrict__ out) {
    int n = (blockIdx.x * blockDim.x + threadIdx.x) >> 5;
    int lane = threadIdx.x & 31;
    if (n >= N_NODES) return;
    int hd = lane >> 3;

    const float4* hrow = (const float4*)(g_h + (size_t)n * HF);
    float4 aA = hrow[lane * 2];
    float4 aB = hrow[lane * 2 + 1];

    float4 adv = *(const float4*)(g_adst + n * HEADS);
    float adn = (hd == 0) ? adv.x : (hd == 1) ? adv.y : (hd == 2) ? adv.z : adv.w;
    float4 asv = *(const float4*)(g_asrc + n * HEADS);
    float e0 = ((hd == 0) ? asv.x : (hd == 1) ? asv.y : (hd == 2) ? asv.z : asv.w) + adn;
    e0 = (e0 > 0.f) ? e0 : NEG_SLOPE * e0;   // self-loop seeds the state
    float m = e0, ssum = 1.0f;

    int lo = g_off[n], hi = g_off[n + 1];

    float4 av, v0, v1;
    if (lo < hi) {
        int s0 = g_csr[lo];
        av = *(const float4*)(g_asrc + s0 * HEADS);
        const float4* hs = (const float4*)(g_h + (size_t)s0 * HF);
        v0 = hs[lane * 2];
        v1 = hs[lane * 2 + 1];
    }
    for (int j = lo; j < hi; j++) {
        float4 cav = av, cv0 = v0, cv1 = v1;
        if (j + 1 < hi) {
            int s1 = g_csr[j + 1];
            av = *(const float4*)(g_asrc + s1 * HEADS);
            const float4* hs = (const float4*)(g_h + (size_t)s1 * HF);
            v0 = hs[lane * 2];
            v1 = hs[lane * 2 + 1];
        }
        float e = ((hd == 0) ? cav.x : (hd == 1) ? cav.y : (hd == 2) ? cav.z : cav.w) + adn;
        e = (e > 0.f) ? e : NEG_SLOPE * e;
        float nm = fmaxf(m, e);
        float corr = __expf(m - nm);
        float w = __expf(e - nm);
        ssum = ssum * corr + w;
        aA.x = aA.x * corr + w * cv0.x;  aA.y = aA.y * corr + w * cv0.y;
        aA.z = aA.z * corr + w * cv0.z;  aA.w = aA.w * corr + w * cv0.w;
        aB.x = aB.x * corr + w * cv1.x;  aB.y = aB.y * corr + w * cv1.y;
        aB.z = aB.z * corr + w * cv1.z;  aB.w = aB.w * corr + w * cv1.w;
        m = nm;
    }

    float inv = 1.0f / ssum;
    float4 b0 = *(const float4*)(bias + lane * 8);
    float4 b1 = *(const float4*)(bias + lane * 8 + 4);
    float4* orow = (float4*)(out + (size_t)n * HF);
    orow[lane * 2]     = make_float4(aA.x * inv + b0.x, aA.y * inv + b0.y,
                                     aA.z * inv + b0.z, aA.w * inv + b0.w);
    orow[lane * 2 + 1] = make_float4(aB.x * inv + b1.x, aB.y * inv + b1.y,
                                     aB.z * inv + b1.z, aB.w * inv + b1.w);
}

// ---------------- launch ----------------------------------------------------
extern "C" void kernel_launch(void* const* d_in, const int* in_sizes, int n_in,
                              void* d_out, int out_size) {
    const float* x     = (const float*)d_in[0];
    const int*   ei    = (const int*)d_in[1];       // int32: JAX x64 disabled
    const float* W     = (const float*)d_in[2];
    const float* att_s = (const float*)d_in[3];
    const float* att_d = (const float*)d_in[4];
    const float* bias  = (const float*)d_in[5];
    float*       out   = (float*)d_out;
    (void)in_sizes; (void)n_in; (void)out_size;

    wsplit_kernel<<<(IN_F * HF + 255) / 256, 256>>>(W);
    gemm_bf16_kernel<<<dim3((N_NODES + 127) / 128, HF / 64), 256>>>(x, att_s, att_d);
    zero_deg_kernel<<<(N_NODES + 255) / 256, 256>>>();
    hist_kernel<<<(N_EDGES + 255) / 256, 256>>>(ei);
    blockred_kernel<<<NBLK, SCAN_CHUNK>>>();
    scanblk_kernel<<<1, 128>>>();
    offsets_kernel<<<NBLK, SCAN_CHUNK>>>();
    scatter_kernel<<<(N_EDGES + 255) / 256, 256>>>(ei);
    sortseg_kernel<<<(N_NODES * 32 + 255) / 256, 256>>>();
    agg_kernel<<<(N_NODES * 32 + 255) / 256, 256>>>(bias, out);
}

// round 15
// speedup vs baseline: 1.4301x; 1.2205x over previous
#include <cuda_runtime.h>
#include <cuda_bf16.h>
#include <cstdint>

#define N_NODES 50000
#define N_EDGES 800000
#define IN_F 256
#define HEADS 4
#define OUT_F 64
#define HF 256            // HEADS * OUT_F
#define NEG_SLOPE 0.2f

#define SCAN_CHUNK 512
#define NBLK ((N_NODES + SCAN_CHUNK - 1) / SCAN_CHUNK)   // 98

// ---------------- scratch (static device allocations; no cudaMalloc) --------
__device__ float g_h[(size_t)N_NODES * HF];      // 51.2 MB  projected features
__device__ __nv_bfloat16 g_Whi[IN_F * HF];
__device__ __nv_bfloat16 g_Wlo[IN_F * HF];
__device__ float g_asrc[N_NODES * HEADS];
__device__ float g_adst[N_NODES * HEADS];
__device__ int   g_deg[N_NODES];
__device__ int   g_off[N_NODES + 1];
__device__ int   g_cursor[N_NODES];
__device__ int   g_csr[N_EDGES];                 // src ids grouped by dst
__device__ int   g_bsum[NBLK];
__device__ int   g_boff[NBLK];

// ---------------- W split: fp32 -> bf16 hi + bf16 residual (tiny) -----------
__global__ void wsplit_kernel(const float* __restrict__ W) {
    int i = blockIdx.x * blockDim.x + threadIdx.x;
    if (i >= IN_F * HF) return;
    float w = W[i];
    __nv_bfloat16 hi = __float2bfloat16(w);
    __nv_bfloat16 lo = __float2bfloat16(w - __bfloat162float(hi));
    g_Whi[i] = hi;
    g_Wlo[i] = lo;
}

// ---------------- GEMM: g_h = x @ W, split-bf16 on tensor cores -------------
// Per k-tile: load fp32 x ONCE, split to hi/lo in registers, stage smem,
// then mma hi*hi + hi*lo + lo*hi (lo*lo dropped, ~2^-16 relative).
// blockIdx.y = head; fused a_src/a_dst epilogue (deterministic, no atomics).
#define ASTRIDE 40   // bf16 elements per A smem row (80B, conflict-free ldmatrix)
#define BSTRIDE 72   // bf16 elements per B smem row (144B)

__device__ __forceinline__ void ldsm4(uint32_t* r, const __nv_bfloat16* p) {
    unsigned a = (unsigned)__cvta_generic_to_shared(p);
    asm volatile("ldmatrix.sync.aligned.m8n8.x4.shared.b16 {%0,%1,%2,%3}, [%4];"
                 : "=r"(r[0]), "=r"(r[1]), "=r"(r[2]), "=r"(r[3]) : "r"(a));
}
__device__ __forceinline__ void ldsm4t(uint32_t* r, const __nv_bfloat16* p) {
    unsigned a = (unsigned)__cvta_generic_to_shared(p);
    asm volatile("ldmatrix.sync.aligned.m8n8.x4.trans.shared.b16 {%0,%1,%2,%3}, [%4];"
                 : "=r"(r[0]), "=r"(r[1]), "=r"(r[2]), "=r"(r[3]) : "r"(a));
}
__device__ __forceinline__ void mma16816(float* c, const uint32_t* a, uint32_t b0, uint32_t b1) {
    asm volatile("mma.sync.aligned.m16n8k16.row.col.f32.bf16.bf16.f32 "
                 "{%0,%1,%2,%3}, {%4,%5,%6,%7}, {%8,%9}, {%0,%1,%2,%3};"
                 : "+f"(c[0]), "+f"(c[1]), "+f"(c[2]), "+f"(c[3])
                 : "r"(a[0]), "r"(a[1]), "r"(a[2]), "r"(a[3]), "r"(b0), "r"(b1));
}

__global__ __launch_bounds__(256) void gemm_bf16_kernel(const float* __restrict__ x,
                                                        const float* __restrict__ att_s,
                                                        const float* __restrict__ att_d) {
    __shared__ __align__(16) __nv_bfloat16 sAhi[128 * ASTRIDE];  // 10240 B
    __shared__ __align__(16) __nv_bfloat16 sAlo[128 * ASTRIDE];  // 10240 B
    __shared__ __align__(16) __nv_bfloat16 sBhi[32 * BSTRIDE];   //  4608 B
    __shared__ __align__(16) __nv_bfloat16 sBlo[32 * BSTRIDE];   //  4608 B
    __shared__ float sds[2][128];   // per-(wn,row) a_src partials
    __shared__ float sdd[2][128];   // per-(wn,row) a_dst partials

    const int tid = threadIdx.x;
    const int lane = tid & 31;
    const int wid = tid >> 5;
    const int wm = wid & 3;        // 4 M-warps of 32 rows
    const int wn = wid >> 2;       // 2 N-warps of 32 cols
    const int mb = blockIdx.x * 128;
    const int hd = blockIdx.y;     // head; nb = hd*64
    const int nb = hd * 64;
    const int lrow = lane & 15;
    const int lcol8 = (lane >> 4) << 3;   // 0 or 8 (bf16 elements)

    float acc[2][4][4];
#pragma unroll
    for (int i = 0; i < 2; i++)
#pragma unroll
        for (int j = 0; j < 4; j++)
#pragma unroll
            for (int k = 0; k < 4; k++) acc[i][j][k] = 0.f;

#pragma unroll 1
    for (int kt = 0; kt < IN_F; kt += 32) {
        // A tile: 128 rows x 32 fp32, loaded once and split in registers.
#pragma unroll
        for (int i = 0; i < 2; i++) {
            int t = tid + i * 256;
            int r = t >> 2, ch = t & 3;           // row, 8-float chunk
            int grow = mb + r;
            float4 xa = make_float4(0.f, 0.f, 0.f, 0.f);
            float4 xb = make_float4(0.f, 0.f, 0.f, 0.f);
            if (grow < N_NODES) {
                const float4* xp = (const float4*)(x + (size_t)grow * IN_F + kt + ch * 8);
                xa = xp[0]; xb = xp[1];
            }
            float xs[8] = {xa.x, xa.y, xa.z, xa.w, xb.x, xb.y, xb.z, xb.w};
            union { __nv_bfloat16 b[8]; uint4 u; } H, L;
#pragma unroll
            for (int q = 0; q < 8; q++) {
                H.b[q] = __float2bfloat16(xs[q]);
                L.b[q] = __float2bfloat16(xs[q] - __bfloat162float(H.b[q]));
            }
            *(uint4*)(sAhi + r * ASTRIDE + ch * 8) = H.u;
            *(uint4*)(sAlo + r * ASTRIDE + ch * 8) = L.u;
        }
        // B tiles: 32 rows x 64 bf16 each, 1 uint4 per thread per tile
        {
            int r = tid >> 3, c16 = tid & 7;
            size_t go = (size_t)(kt + r) * HF + nb + c16 * 8;
            *(uint4*)(sBhi + r * BSTRIDE + c16 * 8) = *(const uint4*)(g_Whi + go);
            *(uint4*)(sBlo + r * BSTRIDE + c16 * 8) = *(const uint4*)(g_Wlo + go);
        }
        __syncthreads();

        uint32_t ah[2][2][4], al[2][2][4], bh[2][2][4], bl[2][2][4];
#pragma unroll
        for (int mt = 0; mt < 2; mt++)
#pragma unroll
            for (int kc = 0; kc < 2; kc++) {
                int off = (wm * 32 + mt * 16 + lrow) * ASTRIDE + kc * 16 + lcol8;
                ldsm4(ah[mt][kc], sAhi + off);
                ldsm4(al[mt][kc], sAlo + off);
            }
#pragma unroll
        for (int kc = 0; kc < 2; kc++)
#pragma unroll
            for (int nt2 = 0; nt2 < 2; nt2++) {
                int off = (kc * 16 + lrow) * BSTRIDE + wn * 32 + nt2 * 16 + lcol8;
                ldsm4t(bh[kc][nt2], sBhi + off);
                ldsm4t(bl[kc][nt2], sBlo + off);
            }
#pragma unroll
        for (int mt = 0; mt < 2; mt++)
#pragma unroll
            for (int nt = 0; nt < 4; nt++)
#pragma unroll
                for (int kc = 0; kc < 2; kc++) {
                    uint32_t* bhp = &bh[kc][nt >> 1][(nt & 1) * 2];
                    uint32_t* blp = &bl[kc][nt >> 1][(nt & 1) * 2];
                    mma16816(acc[mt][nt], ah[mt][kc], bhp[0], bhp[1]);  // hi*hi
                    mma16816(acc[mt][nt], ah[mt][kc], blp[0], blp[1]);  // hi*lo
                    mma16816(acc[mt][nt], al[mt][kc], bhp[0], bhp[1]);  // lo*hi
                }
        __syncthreads();
    }

    // ---- epilogue: store g_h + fused attention dots ----
    const float* wsp = att_s + hd * OUT_F;
    const float* wdp = att_d + hd * OUT_F;

#pragma unroll
    for (int mt = 0; mt < 2; mt++) {
        int row0 = mb + wm * 32 + mt * 16 + (lane >> 2);
        float s0 = 0.f, s1 = 0.f, d0 = 0.f, d1 = 0.f;
#pragma unroll
        for (int nt = 0; nt < 4; nt++) {
            int col = nb + wn * 32 + nt * 8 + (lane & 3) * 2;
            if (row0 < N_NODES)
                *(float2*)(g_h + (size_t)row0 * HF + col) =
                    make_float2(acc[mt][nt][0], acc[mt][nt][1]);
            if (row0 + 8 < N_NODES)
                *(float2*)(g_h + (size_t)(row0 + 8) * HF + col) =
                    make_float2(acc[mt][nt][2], acc[mt][nt][3]);
            int wc = wn * 32 + nt * 8 + (lane & 3) * 2;   // col within head
            float w0 = wsp[wc], w1 = wsp[wc + 1];
            float u0 = wdp[wc], u1 = wdp[wc + 1];
            s0 += acc[mt][nt][0] * w0 + acc[mt][nt][1] * w1;
            d0 += acc[mt][nt][0] * u0 + acc[mt][nt][1] * u1;
            s1 += acc[mt][nt][2] * w0 + acc[mt][nt][3] * w1;
            d1 += acc[mt][nt][2] * u0 + acc[mt][nt][3] * u1;
        }
#pragma unroll
        for (int o = 1; o <= 2; o <<= 1) {
            s0 += __shfl_xor_sync(0xffffffffu, s0, o);
            s1 += __shfl_xor_sync(0xffffffffu, s1, o);
            d0 += __shfl_xor_sync(0xffffffffu, d0, o);
            d1 += __shfl_xor_sync(0xffffffffu, d1, o);
        }
        if ((lane & 3) == 0) {            // unique writer per (wn, local row)
            int lr = wm * 32 + mt * 16 + (lane >> 2);
            sds[wn][lr] = s0;  sdd[wn][lr] = d0;
            sds[wn][lr + 8] = s1;  sdd[wn][lr + 8] = d1;
        }
    }
    __syncthreads();
    if (tid < 128) {                      // fixed-order sum: deterministic
        int grow = mb + tid;
        if (grow < N_NODES) {
            g_asrc[grow * HEADS + hd] = sds[0][tid] + sds[1][tid];
            g_adst[grow * HEADS + hd] = sdd[0][tid] + sdd[1][tid];
        }
    }
}

// ---------------- CSR build (edge_index is int32: JAX x64 is disabled) ------
__global__ void zero_deg_kernel() {
    int i = blockIdx.x * blockDim.x + threadIdx.x;
    if (i < N_NODES) g_deg[i] = 0;
}

__global__ void hist_kernel(const int* __restrict__ ei) {
    int e = blockIdx.x * blockDim.x + threadIdx.x;
    if (e >= N_EDGES) return;
    int d = ei[N_EDGES + e];
    if ((unsigned)d < N_NODES) atomicAdd(&g_deg[d], 1);
}

__global__ __launch_bounds__(SCAN_CHUNK) void blockred_kernel() {
    __shared__ int sh[SCAN_CHUNK];
    int i = blockIdx.x * SCAN_CHUNK + threadIdx.x;
    int v = (i < N_NODES) ? g_deg[i] : 0;
    sh[threadIdx.x] = v;
    __syncthreads();
#pragma unroll
    for (int off = SCAN_CHUNK / 2; off >= 32; off >>= 1) {
        if (threadIdx.x < off) sh[threadIdx.x] += sh[threadIdx.x + off];
        __syncthreads();
    }
    if (threadIdx.x < 32) {
        int s = sh[threadIdx.x];
#pragma unroll
        for (int o = 16; o; o >>= 1) s += __shfl_xor_sync(0xffffffffu, s, o);
        if (threadIdx.x == 0) g_bsum[blockIdx.x] = s;
    }
}

__global__ __launch_bounds__(128) void scanblk_kernel() {
    __shared__ int sh[128];
    int tid = threadIdx.x;
    int v = (tid < NBLK) ? g_bsum[tid] : 0;
    sh[tid] = v;
    __syncthreads();
#pragma unroll
    for (int off = 1; off < 128; off <<= 1) {
        int t = sh[tid];
        if (tid >= off) t += sh[tid - off];
        __syncthreads();
        sh[tid] = t;
        __syncthreads();
    }
    if (tid < NBLK) g_boff[tid] = sh[tid] - v;     // exclusive
    if (tid == 0) g_off[N_NODES] = sh[NBLK - 1];   // total
}

__global__ __launch_bounds__(SCAN_CHUNK) void offsets_kernel() {
    __shared__ int sh[SCAN_CHUNK];
    int tid = threadIdx.x;
    int i = blockIdx.x * SCAN_CHUNK + tid;
    int v = (i < N_NODES) ? g_deg[i] : 0;
    sh[tid] = v;
    __syncthreads();
#pragma unroll
    for (int off = 1; off < SCAN_CHUNK; off <<= 1) {
        int t = sh[tid];
        if (tid >= off) t += sh[tid - off];
        __syncthreads();
        sh[tid] = t;
        __syncthreads();
    }
    if (i < N_NODES) {
        int excl = g_boff[blockIdx.x] + sh[tid] - v;
        g_off[i] = excl;
        g_cursor[i] = excl;
    }
}

__global__ void scatter_kernel(const int* __restrict__ ei) {
    int e = blockIdx.x * blockDim.x + threadIdx.x;
    if (e >= N_EDGES) return;
    int s = ei[e];
    int d = ei[N_EDGES + e];
    if ((unsigned)d >= N_NODES || (unsigned)s >= N_NODES) return;
    int pos = atomicAdd(&g_cursor[d], 1);
    g_csr[pos] = s;
}

// Canonicalize each segment (sorted order) so fp32 accumulation is
// deterministic. len<=32: warp-register bitonic (1 load + 1 store per elem).
// len>32 (rare): odd-even fallback in global memory.
__global__ void sortseg_kernel() {
    int gw = (blockIdx.x * blockDim.x + threadIdx.x) >> 5;
    int lane = threadIdx.x & 31;
    if (gw >= N_NODES) return;
    int lo = g_off[gw], hi = g_off[gw + 1];
    int len = hi - lo;
    if (len < 2) return;
    if (len <= 32) {
        int v = (lane < len) ? g_csr[lo + lane] : 0x7fffffff;
#pragma unroll
        for (int k = 2; k <= 32; k <<= 1) {
#pragma unroll
            for (int j = k >> 1; j > 0; j >>= 1) {
                int p = __shfl_xor_sync(0xffffffffu, v, j);
                bool up = ((lane & k) == 0);
                bool takeMax = (((lane & j) != 0) == up);
                v = takeMax ? max(v, p) : min(v, p);
            }
        }
        if (lane < len) g_csr[lo + lane] = v;
    } else {
        for (int pass = 0; pass < len; pass++) {
            int start = lo + (pass & 1);
            for (int i = start + 2 * lane; i + 1 < hi; i += 64) {
                int a = g_csr[i], b = g_csr[i + 1];
                if (a > b) { g_csr[i] = b; g_csr[i + 1] = a; }
            }
            __syncwarp();
        }
    }
}

// ------- aggregation: warp per node, 4 heads fused, decoupled prefetch ------
// csr index fetched TWO ahead; operands one ahead -> per-iter critical path
// is one L2 trip, not csr->operand chained. Arithmetic order unchanged.
__global__ __launch_bounds__(256) void agg_kernel(const float* __restrict__ bias,
                                                  float* __restrict__ out) {
    int n = (blockIdx.x * blockDim.x + threadIdx.x) >> 5;
    int lane = threadIdx.x & 31;
    if (n >= N_NODES) return;
    int hd = lane >> 3;

    const float4* hrow = (const float4*)(g_h + (size_t)n * HF);
    float4 aA = hrow[lane * 2];
    float4 aB = hrow[lane * 2 + 1];

    float4 adv = *(const float4*)(g_adst + n * HEADS);
    float adn = (hd == 0) ? adv.x : (hd == 1) ? adv.y : (hd == 2) ? adv.z : adv.w;
    float4 asv = *(const float4*)(g_asrc + n * HEADS);
    float e0 = ((hd == 0) ? asv.x : (hd == 1) ? asv.y : (hd == 2) ? asv.z : asv.w) + adn;
    e0 = (e0 > 0.f) ? e0 : NEG_SLOPE * e0;   // self-loop seeds the state
    float m = e0, ssum = 1.0f;

    int lo = g_off[n], hi = g_off[n + 1];

    int sj1 = (lo < hi) ? g_csr[lo] : 0;         // csr for current edge
    int sj2 = (lo + 1 < hi) ? g_csr[lo + 1] : 0; // csr one ahead
    float4 av, v0, v1;
    if (lo < hi) {
        av = *(const float4*)(g_asrc + sj1 * HEADS);
        const float4* hs = (const float4*)(g_h + (size_t)sj1 * HF);
        v0 = hs[lane * 2];
        v1 = hs[lane * 2 + 1];
    }
    for (int j = lo; j < hi; j++) {
        float4 cav = av, cv0 = v0, cv1 = v1;
        int snext = sj2;
        sj2 = (j + 2 < hi) ? g_csr[j + 2] : 0;   // fly independently
        if (j + 1 < hi) {                        // uses already-resident snext
            av = *(const float4*)(g_asrc + snext * HEADS);
            const float4* hs = (const float4*)(g_h + (size_t)snext * HF);
            v0 = hs[lane * 2];
            v1 = hs[lane * 2 + 1];
        }
        float e = ((hd == 0) ? cav.x : (hd == 1) ? cav.y : (hd == 2) ? cav.z : cav.w) + adn;
        e = (e > 0.f) ? e : NEG_SLOPE * e;
        float nm = fmaxf(m, e);
        float corr = __expf(m - nm);
        float w = __expf(e - nm);
        ssum = ssum * corr + w;
        aA.x = aA.x * corr + w * cv0.x;  aA.y = aA.y * corr + w * cv0.y;
        aA.z = aA.z * corr + w * cv0.z;  aA.w = aA.w * corr + w * cv0.w;
        aB.x = aB.x * corr + w * cv1.x;  aB.y = aB.y * corr + w * cv1.y;
        aB.z = aB.z * corr + w * cv1.z;  aB.w = aB.w * corr + w * cv1.w;
        m = nm;
    }

    float inv = 1.0f / ssum;
    float4 b0 = *(const float4*)(bias + lane * 8);
    float4 b1 = *(const float4*)(bias + lane * 8 + 4);
    float4* orow = (float4*)(out + (size_t)n * HF);
    orow[lane * 2]     = make_float4(aA.x * inv + b0.x, aA.y * inv + b0.y,
                                     aA.z * inv + b0.z, aA.w * inv + b0.w);
    orow[lane * 2 + 1] = make_float4(aB.x * inv + b1.x, aB.y * inv + b1.y,
                                     aB.z * inv + b1.z, aB.w * inv + b1.w);
}

// ---------------- launch ----------------------------------------------------
extern "C" void kernel_launch(void* const* d_in, const int* in_sizes, int n_in,
                              void* d_out, int out_size) {
    const float* x     = (const float*)d_in[0];
    const int*   ei    = (const int*)d_in[1];       // int32: JAX x64 disabled
    const float* W     = (const float*)d_in[2];
    const float* att_s = (const float*)d_in[3];
    const float* att_d = (const float*)d_in[4];
    const float* bias  = (const float*)d_in[5];
    float*       out   = (float*)d_out;
    (void)in_sizes; (void)n_in; (void)out_size;

    wsplit_kernel<<<(IN_F * HF + 255) / 256, 256>>>(W);
    gemm_bf16_kernel<<<dim3((N_NODES + 127) / 128, HF / 64), 256>>>(x, att_s, att_d);
    zero_deg_kernel<<<(N_NODES + 255) / 256, 256>>>();
    hist_kernel<<<(N_EDGES + 255) / 256, 256>>>(ei);
    blockred_kernel<<<NBLK, SCAN_CHUNK>>>();
    scanblk_kernel<<<1, 128>>>();
    offsets_kernel<<<NBLK, SCAN_CHUNK>>>();
    scatter_kernel<<<(N_EDGES + 255) / 256, 256>>>(ei);
    sortseg_kernel<<<(N_NODES * 32 + 255) / 256, 256>>>();
    agg_kernel<<<(N_NODES * 32 + 255) / 256, 256>>>(bias, out);
}

// round 17
// speedup vs baseline: 1.4438x; 1.0096x over previous
#include <cuda_runtime.h>
#include <cuda_bf16.h>
#include <cstdint>

#define N_NODES 50000
#define N_EDGES 800000
#define IN_F 256
#define HEADS 4
#define OUT_F 64
#define HF 256            // HEADS * OUT_F
#define NEG_SLOPE 0.2f

#define SCAN_CHUNK 512
#define NBLK ((N_NODES + SCAN_CHUNK - 1) / SCAN_CHUNK)   // 98

// ---------------- scratch (static device allocations; no cudaMalloc) --------
__device__ float g_h[(size_t)N_NODES * HF];      // 51.2 MB  projected features
__device__ __nv_bfloat16 g_Whi[IN_F * HF];
__device__ __nv_bfloat16 g_Wlo[IN_F * HF];
__device__ float g_asrc[N_NODES * HEADS];
__device__ float g_adst[N_NODES * HEADS];
__device__ int   g_deg[N_NODES];
__device__ int   g_off[N_NODES + 1];
__device__ int   g_cursor[N_NODES];
__device__ int   g_csr[N_EDGES];                 // src ids grouped by dst
__device__ int   g_bsum[NBLK];
__device__ int   g_boff[NBLK];

// ---------------- W split: fp32 -> bf16 hi + bf16 residual (tiny) -----------
__global__ void wsplit_kernel(const float* __restrict__ W) {
    int i = blockIdx.x * blockDim.x + threadIdx.x;
    if (i >= IN_F * HF) return;
    float w = W[i];
    __nv_bfloat16 hi = __float2bfloat16(w);
    __nv_bfloat16 lo = __float2bfloat16(w - __bfloat162float(hi));
    g_Whi[i] = hi;
    g_Wlo[i] = lo;
}

// ---------------- GEMM: g_h = x @ W, split-bf16 on tensor cores -------------
// BM=64, BN=256 (ALL heads per block -> x read/split exactly once), BK=16.
// warp (wm,wn): rows wm*32..+32, head wn. Fused a_src/a_dst: unique warp per
// (row, head) -> direct store after quad reduce, no smem, deterministic.
#define ASTRIDE 40    // bf16 elems per A smem row (80B, proven conflict-free)
#define BSTRIDE 264   // bf16 elems per B smem row (528B; 528%128==16, same
                      // residue class as the proven 144B stride)

__device__ __forceinline__ void ldsm4(uint32_t* r, const __nv_bfloat16* p) {
    unsigned a = (unsigned)__cvta_generic_to_shared(p);
    asm volatile("ldmatrix.sync.aligned.m8n8.x4.shared.b16 {%0,%1,%2,%3}, [%4];"
                 : "=r"(r[0]), "=r"(r[1]), "=r"(r[2]), "=r"(r[3]) : "r"(a));
}
__device__ __forceinline__ void ldsm4t(uint32_t* r, const __nv_bfloat16* p) {
    unsigned a = (unsigned)__cvta_generic_to_shared(p);
    asm volatile("ldmatrix.sync.aligned.m8n8.x4.trans.shared.b16 {%0,%1,%2,%3}, [%4];"
                 : "=r"(r[0]), "=r"(r[1]), "=r"(r[2]), "=r"(r[3]) : "r"(a));
}
__device__ __forceinline__ void mma16816(float* c, const uint32_t* a, uint32_t b0, uint32_t b1) {
    asm volatile("mma.sync.aligned.m16n8k16.row.col.f32.bf16.bf16.f32 "
                 "{%0,%1,%2,%3}, {%4,%5,%6,%7}, {%8,%9}, {%0,%1,%2,%3};"
                 : "+f"(c[0]), "+f"(c[1]), "+f"(c[2]), "+f"(c[3])
                 : "r"(a[0]), "r"(a[1]), "r"(a[2]), "r"(a[3]), "r"(b0), "r"(b1));
}

__global__ __launch_bounds__(256) void gemm_bf16_kernel(const float* __restrict__ x,
                                                        const float* __restrict__ att_s,
                                                        const float* __restrict__ att_d) {
    __shared__ __align__(16) __nv_bfloat16 sAhi[64 * ASTRIDE];   // 5120 B
    __shared__ __align__(16) __nv_bfloat16 sAlo[64 * ASTRIDE];   // 5120 B
    __shared__ __align__(16) __nv_bfloat16 sBhi[16 * BSTRIDE];   // 8448 B
    __shared__ __align__(16) __nv_bfloat16 sBlo[16 * BSTRIDE];   // 8448 B

    const int tid = threadIdx.x;
    const int lane = tid & 31;
    const int wid = tid >> 5;
    const int wm = wid & 1;        // 2 M-warps of 32 rows
    const int wn = wid >> 1;       // 4 N-warps = 4 heads
    const int mb = blockIdx.x * 64;
    const int lrow = lane & 15;
    const int lcol8 = (lane >> 4) << 3;   // 0 or 8 (bf16 elements)

    float acc[2][8][4];            // mt, nt(8 n8-tiles = 64 cols), frag
#pragma unroll
    for (int i = 0; i < 2; i++)
#pragma unroll
        for (int j = 0; j < 8; j++)
#pragma unroll
            for (int k = 0; k < 4; k++) acc[i][j][k] = 0.f;

#pragma unroll 1
    for (int kt = 0; kt < IN_F; kt += 16) {
        // A tile: 64 rows x 16 fp32, one float4 per thread, split in regs
        {
            int r = tid >> 2, ch = tid & 3;       // row, 4-float chunk
            int grow = mb + r;
            float4 xa = make_float4(0.f, 0.f, 0.f, 0.f);
            if (grow < N_NODES)
                xa = *(const float4*)(x + (size_t)grow * IN_F + kt + ch * 4);
            float xs[4] = {xa.x, xa.y, xa.z, xa.w};
            union { __nv_bfloat16 b[4]; uint2 u; } H, L;
#pragma unroll
            for (int q = 0; q < 4; q++) {
                H.b[q] = __float2bfloat16(xs[q]);
                L.b[q] = __float2bfloat16(xs[q] - __bfloat162float(H.b[q]));
            }
            *(uint2*)(sAhi + r * ASTRIDE + ch * 4) = H.u;
            *(uint2*)(sAlo + r * ASTRIDE + ch * 4) = L.u;
        }
        // B tiles: 16 rows x 256 bf16 each; 512 uint4 tasks, 2 per thread
#pragma unroll
        for (int i = 0; i < 2; i++) {
            int t = tid + i * 256;
            int r = t >> 5, c16 = t & 31;
            size_t go = (size_t)(kt + r) * HF + c16 * 8;
            *(uint4*)(sBhi + r * BSTRIDE + c16 * 8) = *(const uint4*)(g_Whi + go);
            *(uint4*)(sBlo + r * BSTRIDE + c16 * 8) = *(const uint4*)(g_Wlo + go);
        }
        __syncthreads();

        uint32_t ah[2][4], al[2][4], bh[4][4], bl[4][4];
#pragma unroll
        for (int mt = 0; mt < 2; mt++) {
            int off = (wm * 32 + mt * 16 + lrow) * ASTRIDE + lcol8;
            ldsm4(ah[mt], sAhi + off);
            ldsm4(al[mt], sAlo + off);
        }
#pragma unroll
        for (int pr = 0; pr < 4; pr++) {          // 4 pairs of n8 = 64 cols
            int off = lrow * BSTRIDE + wn * 64 + pr * 16 + lcol8;
            ldsm4t(bh[pr], sBhi + off);
            ldsm4t(bl[pr], sBlo + off);
        }
#pragma unroll
        for (int mt = 0; mt < 2; mt++)
#pragma unroll
            for (int nt = 0; nt < 8; nt++) {
                uint32_t* bhp = &bh[nt >> 1][(nt & 1) * 2];
                uint32_t* blp = &bl[nt >> 1][(nt & 1) * 2];
                mma16816(acc[mt][nt], ah[mt], bhp[0], bhp[1]);  // hi*hi
                mma16816(acc[mt][nt], ah[mt], blp[0], blp[1]);  // hi*lo
                mma16816(acc[mt][nt], al[mt], bhp[0], bhp[1]);  // lo*hi
            }
        __syncthreads();
    }

    // ---- epilogue: store g_h + fused attention dots (direct, no smem) ----
    const float* wsp = att_s + wn * OUT_F;
    const float* wdp = att_d + wn * OUT_F;

#pragma unroll
    for (int mt = 0; mt < 2; mt++) {
        int row0 = mb + wm * 32 + mt * 16 + (lane >> 2);
        float s0 = 0.f, s1 = 0.f, d0 = 0.f, d1 = 0.f;
#pragma unroll
        for (int nt = 0; nt < 8; nt++) {
            int col = wn * 64 + nt * 8 + (lane & 3) * 2;
            if (row0 < N_NODES)
                *(float2*)(g_h + (size_t)row0 * HF + col) =
                    make_float2(acc[mt][nt][0], acc[mt][nt][1]);
            if (row0 + 8 < N_NODES)
                *(float2*)(g_h + (size_t)(row0 + 8) * HF + col) =
                    make_float2(acc[mt][nt][2], acc[mt][nt][3]);
            int wc = nt * 8 + (lane & 3) * 2;     // col within head
            float w0 = wsp[wc], w1 = wsp[wc + 1];
            float u0 = wdp[wc], u1 = wdp[wc + 1];
            s0 += acc[mt][nt][0] * w0 + acc[mt][nt][1] * w1;
            d0 += acc[mt][nt][0] * u0 + acc[mt][nt][1] * u1;
            s1 += acc[mt][nt][2] * w0 + acc[mt][nt][3] * w1;
            d1 += acc[mt][nt][2] * u0 + acc[mt][nt][3] * u1;
        }
#pragma unroll
        for (int o = 1; o <= 2; o <<= 1) {        // quad reduce (same row)
            s0 += __shfl_xor_sync(0xffffffffu, s0, o);
            s1 += __shfl_xor_sync(0xffffffffu, s1, o);
            d0 += __shfl_xor_sync(0xffffffffu, d0, o);
            d1 += __shfl_xor_sync(0xffffffffu, d1, o);
        }
        if ((lane & 3) == 0) {                    // unique warp per (row,head)
            if (row0 < N_NODES) {
                g_asrc[row0 * HEADS + wn] = s0;
                g_adst[row0 * HEADS + wn] = d0;
            }
            if (row0 + 8 < N_NODES) {
                g_asrc[(row0 + 8) * HEADS + wn] = s1;
                g_adst[(row0 + 8) * HEADS + wn] = d1;
            }
        }
    }
}

// ---------------- CSR build (edge_index is int32: JAX x64 is disabled) ------
__global__ void zero_deg_kernel() {
    int i = blockIdx.x * blockDim.x + threadIdx.x;
    if (i < N_NODES) g_deg[i] = 0;
}

__global__ void hist_kernel(const int* __restrict__ ei) {
    int e = blockIdx.x * blockDim.x + threadIdx.x;
    if (e >= N_EDGES) return;
    int d = ei[N_EDGES + e];
    if ((unsigned)d < N_NODES) atomicAdd(&g_deg[d], 1);
}

__global__ __launch_bounds__(SCAN_CHUNK) void blockred_kernel() {
    __shared__ int sh[SCAN_CHUNK];
    int i = blockIdx.x * SCAN_CHUNK + threadIdx.x;
    int v = (i < N_NODES) ? g_deg[i] : 0;
    sh[threadIdx.x] = v;
    __syncthreads();
#pragma unroll
    for (int off = SCAN_CHUNK / 2; off >= 32; off >>= 1) {
        if (threadIdx.x < off) sh[threadIdx.x] += sh[threadIdx.x + off];
        __syncthreads();
    }
    if (threadIdx.x < 32) {
        int s = sh[threadIdx.x];
#pragma unroll
        for (int o = 16; o; o >>= 1) s += __shfl_xor_sync(0xffffffffu, s, o);
        if (threadIdx.x == 0) g_bsum[blockIdx.x] = s;
    }
}

__global__ __launch_bounds__(128) void scanblk_kernel() {
    __shared__ int sh[128];
    int tid = threadIdx.x;
    int v = (tid < NBLK) ? g_bsum[tid] : 0;
    sh[tid] = v;
    __syncthreads();
#pragma unroll
    for (int off = 1; off < 128; off <<= 1) {
        int t = sh[tid];
        if (tid >= off) t += sh[tid - off];
        __syncthreads();
        sh[tid] = t;
        __syncthreads();
    }
    if (tid < NBLK) g_boff[tid] = sh[tid] - v;     // exclusive
    if (tid == 0) g_off[N_NODES] = sh[NBLK - 1];   // total
}

__global__ __launch_bounds__(SCAN_CHUNK) void offsets_kernel() {
    __shared__ int sh[SCAN_CHUNK];
    int tid = threadIdx.x;
    int i = blockIdx.x * SCAN_CHUNK + tid;
    int v = (i < N_NODES) ? g_deg[i] : 0;
    sh[tid] = v;
    __syncthreads();
#pragma unroll
    for (int off = 1; off < SCAN_CHUNK; off <<= 1) {
        int t = sh[tid];
        if (tid >= off) t += sh[tid - off];
        __syncthreads();
        sh[tid] = t;
        __syncthreads();
    }
    if (i < N_NODES) {
        int excl = g_boff[blockIdx.x] + sh[tid] - v;
        g_off[i] = excl;
        g_cursor[i] = excl;
    }
}

__global__ void scatter_kernel(const int* __restrict__ ei) {
    int e = blockIdx.x * blockDim.x + threadIdx.x;
    if (e >= N_EDGES) return;
    int s = ei[e];
    int d = ei[N_EDGES + e];
    if ((unsigned)d >= N_NODES || (unsigned)s >= N_NODES) return;
    int pos = atomicAdd(&g_cursor[d], 1);
    g_csr[pos] = s;
}

// Canonicalize each segment (sorted order) so fp32 accumulation is
// deterministic. len<=32: warp-register bitonic. len>32: odd-even fallback.
__global__ void sortseg_kernel() {
    int gw = (blockIdx.x * blockDim.x + threadIdx.x) >> 5;
    int lane = threadIdx.x & 31;
    if (gw >= N_NODES) return;
    int lo = g_off[gw], hi = g_off[gw + 1];
    int len = hi - lo;
    if (len < 2) return;
    if (len <= 32) {
        int v = (lane < len) ? g_csr[lo + lane] : 0x7fffffff;
#pragma unroll
        for (int k = 2; k <= 32; k <<= 1) {
#pragma unroll
            for (int j = k >> 1; j > 0; j >>= 1) {
                int p = __shfl_xor_sync(0xffffffffu, v, j);
                bool up = ((lane & k) == 0);
                bool takeMax = (((lane & j) != 0) == up);
                v = takeMax ? max(v, p) : min(v, p);
            }
        }
        if (lane < len) g_csr[lo + lane] = v;
    } else {
        for (int pass = 0; pass < len; pass++) {
            int start = lo + (pass & 1);
            for (int i = start + 2 * lane; i + 1 < hi; i += 64) {
                int a = g_csr[i], b = g_csr[i + 1];
                if (a > b) { g_csr[i] = b; g_csr[i + 1] = a; }
            }
            __syncwarp();
        }
    }
}

// ------- aggregation: warp per node, 4 heads fused, decoupled prefetch ------
__global__ __launch_bounds__(256) void agg_kernel(const float* __restrict__ bias,
                                                  float* __restrict__ out) {
    int n = (blockIdx.x * blockDim.x + threadIdx.x) >> 5;
    int lane = threadIdx.x & 31;
    if (n >= N_NODES) return;
    int hd = lane >> 3;

    const float4* hrow = (const float4*)(g_h + (size_t)n * HF);
    float4 aA = hrow[lane * 2];
    float4 aB = hrow[lane * 2 + 1];

    float4 adv = *(const float4*)(g_adst + n * HEADS);
    float adn = (hd == 0) ? adv.x : (hd == 1) ? adv.y : (hd == 2) ? adv.z : adv.w;
    float4 asv = *(const float4*)(g_asrc + n * HEADS);
    float e0 = ((hd == 0) ? asv.x : (hd == 1) ? asv.y : (hd == 2) ? asv.z : asv.w) + adn;
    e0 = (e0 > 0.f) ? e0 : NEG_SLOPE * e0;   // self-loop seeds the state
    float m = e0, ssum = 1.0f;

    int lo = g_off[n], hi = g_off[n + 1];

    int sj1 = (lo < hi) ? g_csr[lo] : 0;         // csr for current edge
    int sj2 = (lo + 1 < hi) ? g_csr[lo + 1] : 0; // csr one ahead
    float4 av, v0, v1;
    if (lo < hi) {
        av = *(const float4*)(g_asrc + sj1 * HEADS);
        const float4* hs = (const float4*)(g_h + (size_t)sj1 * HF);
        v0 = hs[lane * 2];
        v1 = hs[lane * 2 + 1];
    }
    for (int j = lo; j < hi; j++) {
        float4 cav = av, cv0 = v0, cv1 = v1;
        int snext = sj2;
        sj2 = (j + 2 < hi) ? g_csr[j + 2] : 0;   // fly independently
        if (j + 1 < hi) {                        // uses already-resident snext
            av = *(const float4*)(g_asrc + snext * HEADS);
            const float4* hs = (const float4*)(g_h + (size_t)snext * HF);
            v0 = hs[lane * 2];
            v1 = hs[lane * 2 + 1];
        }
        float e = ((hd == 0) ? cav.x : (hd == 1) ? cav.y : (hd == 2) ? cav.z : cav.w) + adn;
        e = (e > 0.f) ? e : NEG_SLOPE * e;
        float nm = fmaxf(m, e);
        float corr = __expf(m - nm);
        float w = __expf(e - nm);
        ssum = ssum * corr + w;
        aA.x = aA.x * corr + w * cv0.x;  aA.y = aA.y * corr + w * cv0.y;
        aA.z = aA.z * corr + w * cv0.z;  aA.w = aA.w * corr + w * cv0.w;
        aB.x = aB.x * corr + w * cv1.x;  aB.y = aB.y * corr + w * cv1.y;
        aB.z = aB.z * corr + w * cv1.z;  aB.w = aB.w * corr + w * cv1.w;
        m = nm;
    }

    float inv = 1.0f / ssum;
    float4 b0 = *(const float4*)(bias + lane * 8);
    float4 b1 = *(const float4*)(bias + lane * 8 + 4);
    float4* orow = (float4*)(out + (size_t)n * HF);
    orow[lane * 2]     = make_float4(aA.x * inv + b0.x, aA.y * inv + b0.y,
                                     aA.z * inv + b0.z, aA.w * inv + b0.w);
    orow[lane * 2 + 1] = make_float4(aB.x * inv + b1.x, aB.y * inv + b1.y,
                                     aB.z * inv + b1.z, aB.w * inv + b1.w);
}

// ---------------- launch ----------------------------------------------------
extern "C" void kernel_launch(void* const* d_in, const int* in_sizes, int n_in,
                              void* d_out, int out_size) {
    const float* x     = (const float*)d_in[0];
    const int*   ei    = (const int*)d_in[1];       // int32: JAX x64 disabled
    const float* W     = (const float*)d_in[2];
    const float* att_s = (const float*)d_in[3];
    const float* att_d = (const float*)d_in[4];
    const float* bias  = (const float*)d_in[5];
    float*       out   = (float*)d_out;
    (void)in_sizes; (void)n_in; (void)out_size;

    wsplit_kernel<<<(IN_F * HF + 255) / 256, 256>>>(W);
    gemm_bf16_kernel<<<(N_NODES + 63) / 64, 256>>>(x, att_s, att_d);
    zero_deg_kernel<<<(N_NODES + 255) / 256, 256>>>();
    hist_kernel<<<(N_EDGES + 255) / 256, 256>>>(ei);
    blockred_kernel<<<NBLK, SCAN_CHUNK>>>();
    scanblk_kernel<<<1, 128>>>();
    offsets_kernel<<<NBLK, SCAN_CHUNK>>>();
    scatter_kernel<<<(N_EDGES + 255) / 256, 256>>>(ei);
    sortseg_kernel<<<(N_NODES * 32 + 255) / 256, 256>>>();
    agg_kernel<<<(N_NODES * 32 + 255) / 256, 256>>>(bias, out);
}